// round 15
// baseline (speedup 1.0000x reference)
#include <cuda_runtime.h>
#include <cuda_bf16.h>
#include <cuda_fp16.h>
#include <cstdint>

#define HW 16384
#define CC 768
#define EPSF 1e-8f
#define NCH 12           // 768 / 64 K-chunks
#define NJB 128          // 16384 / 128 j-blocks
#define BK 64

// ---------------- scratch (device globals; no allocs allowed) ----------------
__device__ __align__(16) __half g_Ahat[(size_t)HW * CC];          // centered-normalized fp16, (i,c)
__device__ __align__(16) __half g_Bhat[(size_t)HW * CC];
__device__ __align__(16) __nv_bfloat16 g_Araw[(size_t)HW * CC];   // raw-normalized (loss)
__device__ __align__(16) __nv_bfloat16 g_Braw[(size_t)HW * CC];
__device__ float g_mean[2][CC];
__device__ unsigned long long g_part[(size_t)NJB * HW];
__device__ int   g_z[HW];
__device__ float g_pl[HW / 8];

// ---------------- helpers ----------------
static __device__ __forceinline__ uint32_t smem_u32(const void* p) {
    uint32_t a;
    asm("{ .reg .u64 t; cvta.to.shared.u64 t, %1; cvt.u32.u64 %0, t; }" : "=r"(a) : "l"(p));
    return a;
}
static __device__ __forceinline__ uint32_t sortable(float f) {
    uint32_t u = __float_as_uint(f);
    return (u & 0x80000000u) ? ~u : (u | 0x80000000u);
}

// ---------------- block reduce (sum) ----------------
static __device__ __forceinline__ float blk_sum(float v) {
    __shared__ float smr[32];
    int lane = threadIdx.x & 31, w = threadIdx.x >> 5;
    #pragma unroll
    for (int o = 16; o; o >>= 1) v += __shfl_down_sync(0xffffffffu, v, o);
    if (lane == 0) smr[w] = v;
    __syncthreads();
    if (w == 0) {
        v = (lane < (int)(blockDim.x >> 5)) ? smr[lane] : 0.f;
        #pragma unroll
        for (int o = 16; o; o >>= 1) v += __shfl_down_sync(0xffffffffu, v, o);
    }
    return v;  // valid in thread 0
}

// ---------------- 1) per-channel means (float4 loads) ----------------
__global__ void k_mean(const float* __restrict__ x, const float* __restrict__ s) {
    const float* p = blockIdx.y ? s : x;
    const float4* row = (const float4*)(p + (size_t)blockIdx.x * HW);
    float acc = 0.f;
    #pragma unroll 4
    for (int i = threadIdx.x; i < HW / 4; i += 256) {
        float4 v = row[i];
        acc += (v.x + v.y) + (v.z + v.w);
    }
    float t = blk_sum(acc);
    if (threadIdx.x == 0) g_mean[blockIdx.y][blockIdx.x] = t * (1.0f / HW);
}

// ---------------- 2) fused norms + fp16 hat + bf16 raw, 4 threads/position ------
__global__ void __launch_bounds__(256) k_normhat(const float* __restrict__ x,
                                                 const float* __restrict__ s) {
    extern __shared__ char dummy[];   // occupancy cap only
    (void)dummy;
    const int m = blockIdx.y;
    const float* p = m ? s : x;
    __half* dh = m ? g_Bhat : g_Ahat;
    __nv_bfloat16* dr = m ? g_Braw : g_Araw;
    const int i = blockIdx.x * 64 + (threadIdx.x >> 2);
    const int q = threadIdx.x & 3;          // channel quarter [q*192, q*192+192)
    const int c0 = q * 192;

    float ac = 0.f, ar = 0.f;
    #pragma unroll 8
    for (int k = 0; k < 192; k++) {
        int c = c0 + k;
        float v = p[(size_t)c * HW + i];
        float d = v - g_mean[m][c];
        ac = fmaf(d, d, ac);
        ar = fmaf(v, v, ar);
    }
    #pragma unroll
    for (int o = 1; o < 4; o <<= 1) {
        ac += __shfl_xor_sync(0xffffffffu, ac, o);
        ar += __shfl_xor_sync(0xffffffffu, ar, o);
    }
    float invc = 1.0f / (sqrtf(ac + EPSF) + EPSF);
    float invr = 1.0f / (sqrtf(ar) + EPSF);

    for (int k = 0; k < 192; k += 8) {
        uint4 wh, wr;
        uint32_t* ph = (uint32_t*)&wh;
        uint32_t* pr = (uint32_t*)&wr;
        #pragma unroll
        for (int u = 0; u < 4; u++) {
            int c = c0 + k + 2 * u;
            float v0 = p[(size_t)c * HW + i];
            float v1 = p[(size_t)(c + 1) * HW + i];
            __half2 h = __floats2half2_rn((v0 - g_mean[m][c]) * invc,
                                          (v1 - g_mean[m][c + 1]) * invc);
            __nv_bfloat162 r = __floats2bfloat162_rn(v0 * invr, v1 * invr);
            ph[u] = *(const uint32_t*)&h;
            pr[u] = *(const uint32_t*)&r;
        }
        *(uint4*)(dh + (size_t)i * CC + c0 + k) = wh;
        *(uint4*)(dr + (size_t)i * CC + c0 + k) = wr;
    }
}

// ---------------- 3) HMMA GEMM (128x128 tile, fp16 accum) + fused row argmax ----
// smem: 3 stages x (A 128x64 fp16 = 16KB + B 16KB) = 96KB, SW128 swizzle.
__global__ void __launch_bounds__(256) k_gemm() {
    extern __shared__ char sm[];
    const int tid = threadIdx.x, wid = tid >> 5, lid = tid & 31;
    const int wm = wid >> 2, wn = wid & 3;       // warp 64x32 tile at (wm*64, wn*32)
    const uint32_t sbase = smem_u32(sm);

    const __half* Ag = g_Ahat + (size_t)blockIdx.y * 128 * CC;
    const __half* Bg = g_Bhat + (size_t)blockIdx.x * 128 * CC;

    const int lrow = tid >> 3;          // 0..31 base row (stride 32 over 4 passes)
    const int lq   = tid & 7;           // 16B chunk within 128B row

    auto load_stage = [&](int stg, int kc) {
        uint32_t abase = sbase + (uint32_t)stg * 32768u;
        uint32_t bbase = abase + 16384u;
        const __half* ga = Ag + kc * BK;
        const __half* gb = Bg + kc * BK;
        #pragma unroll
        for (int ps = 0; ps < 4; ps++) {
            int row = lrow + ps * 32;
            uint32_t off = (uint32_t)(row * 128 + lq * 16);
            uint32_t sw = off ^ ((off >> 3) & 0x70);
            const char* pa = (const char*)(ga + (size_t)row * CC) + lq * 16;
            const char* pb = (const char*)(gb + (size_t)row * CC) + lq * 16;
            asm volatile("cp.async.cg.shared.global [%0], [%1], 16;" :: "r"(abase + sw), "l"(pa));
            asm volatile("cp.async.cg.shared.global [%0], [%1], 16;" :: "r"(bbase + sw), "l"(pb));
        }
        asm volatile("cp.async.commit_group;" ::: "memory");
    };

    // fp16 accumulators: 2 regs (half2 x2) per 16x8 tile
    uint32_t acc[4][4][2];
    #pragma unroll
    for (int a = 0; a < 4; a++)
        #pragma unroll
        for (int b = 0; b < 4; b++) { acc[a][b][0] = 0u; acc[a][b][1] = 0u; }

    load_stage(0, 0);
    load_stage(1, 1);

    const int mrow8 = lid & 7;   // row within 8x8
    const int mat   = lid >> 3;  // which of 4 matrices

    for (int kc = 0; kc < NCH; kc++) {
        if (kc + 1 < NCH) {
            asm volatile("cp.async.wait_group 1;" ::: "memory");
        } else {
            asm volatile("cp.async.wait_group 0;" ::: "memory");
        }
        __syncthreads();                                // single barrier per iteration
        if (kc + 2 < NCH) load_stage((kc + 2) % 3, kc + 2);

        uint32_t abase = sbase + (uint32_t)(kc % 3) * 32768u;
        uint32_t bbase = abase + 16384u;

        #pragma unroll
        for (int k16 = 0; k16 < 4; k16++) {
            const int k0 = k16 * 16;
            uint32_t af[4][4];
            #pragma unroll
            for (int mt = 0; mt < 4; mt++) {
                int row = wm * 64 + mt * 16 + (mat & 1) * 8 + mrow8;
                int kcol = k0 + (mat >> 1) * 8;
                uint32_t off = (uint32_t)(row * 128 + kcol * 2);
                uint32_t sw = abase + (off ^ ((off >> 3) & 0x70));
                asm volatile("ldmatrix.sync.aligned.m8n8.x4.shared.b16 {%0,%1,%2,%3}, [%4];"
                             : "=r"(af[mt][0]), "=r"(af[mt][1]), "=r"(af[mt][2]), "=r"(af[mt][3])
                             : "r"(sw));
            }
            uint32_t bf[4][2];
            #pragma unroll
            for (int g = 0; g < 2; g++) {
                int nrow = wn * 32 + g * 16 + (mat >> 1) * 8 + mrow8;
                int kcol = k0 + (mat & 1) * 8;
                uint32_t off = (uint32_t)(nrow * 128 + kcol * 2);
                uint32_t sw = bbase + (off ^ ((off >> 3) & 0x70));
                asm volatile("ldmatrix.sync.aligned.m8n8.x4.shared.b16 {%0,%1,%2,%3}, [%4];"
                             : "=r"(bf[g * 2][0]), "=r"(bf[g * 2][1]),
                               "=r"(bf[g * 2 + 1][0]), "=r"(bf[g * 2 + 1][1])
                             : "r"(sw));
            }
            #pragma unroll
            for (int mt = 0; mt < 4; mt++)
                #pragma unroll
                for (int nt = 0; nt < 4; nt++)
                    asm volatile(
                        "mma.sync.aligned.m16n8k16.row.col.f16.f16.f16.f16 "
                        "{%0,%1}, {%2,%3,%4,%5}, {%6,%7}, {%0,%1};"
                        : "+r"(acc[mt][nt][0]), "+r"(acc[mt][nt][1])
                        : "r"(af[mt][0]), "r"(af[mt][1]), "r"(af[mt][2]), "r"(af[mt][3]),
                          "r"(bf[nt][0]), "r"(bf[nt][1]));
        }
    }

    // ---- epilogue: row argmax over the 128-col tile ----
    unsigned long long* red = (unsigned long long*)sm;  // [128][4] overlay (loads all done)
    const int quad = lid >> 2, qlan = lid & 3;
    #pragma unroll
    for (int mt = 0; mt < 4; mt++) {
        #pragma unroll
        for (int h = 0; h < 2; h++) {                  // h=0: rows 0-7, h=1: rows 8-15
            unsigned long long pk = 0ull;
            #pragma unroll
            for (int nt = 0; nt < 4; nt++) {
                float2 fv = __half22float2(*(const __half2*)&acc[mt][nt][h]);
                #pragma unroll
                for (int e = 0; e < 2; e++) {
                    float v = e ? fv.y : fv.x;
                    int j = blockIdx.x * 128 + wn * 32 + nt * 8 + qlan * 2 + e;
                    unsigned long long cand =
                        ((unsigned long long)sortable(v) << 32) | (uint32_t)(0xFFFFFFFFu - j);
                    if (cand > pk) pk = cand;
                }
            }
            #pragma unroll
            for (int off = 1; off < 4; off <<= 1) {
                unsigned long long o = __shfl_xor_sync(0xffffffffu, pk, off);
                if (o > pk) pk = o;
            }
            if (qlan == 0) {
                int row = wm * 64 + mt * 16 + h * 8 + quad;
                red[row * 4 + wn] = pk;
            }
        }
    }
    __syncthreads();
    if (tid < 128) {
        unsigned long long pk = red[tid * 4];
        #pragma unroll
        for (int w = 1; w < 4; w++) {
            unsigned long long o = red[tid * 4 + w];
            if (o > pk) pk = o;
        }
        g_part[(size_t)blockIdx.x * HW + blockIdx.y * 128 + tid] = pk;
    }
}

// ---------------- 4) reduce partials -> z[i], 4 threads per position ------------
__global__ void k_reduce() {
    const int i = blockIdx.x * 64 + (threadIdx.x >> 2);
    const int q = threadIdx.x & 3;
    unsigned long long best = 0ull;
    #pragma unroll 8
    for (int k = 0; k < 32; k++) {
        unsigned long long v = g_part[(size_t)(q + 4 * k) * HW + i];
        if (v > best) best = v;
    }
    #pragma unroll
    for (int o = 1; o < 4; o <<= 1) {
        unsigned long long t = __shfl_xor_sync(0xffffffffu, best, o);
        if (t > best) best = t;
    }
    if (q == 0) g_z[i] = (int)(0xFFFFFFFFu - (uint32_t)best);
}

// ---------------- 5) gathered raw-cosine loss, warp-per-position ----------------
__global__ void k_loss() {
    const int w = threadIdx.x >> 5, lane = threadIdx.x & 31;
    const int i = blockIdx.x * 8 + w;
    const int z = g_z[i];
    const uint4* ra = (const uint4*)(g_Araw + (size_t)i * CC);
    const uint4* rb = (const uint4*)(g_Braw + (size_t)z * CC);
    float acc = 0.f;
    #pragma unroll
    for (int t = 0; t < 3; t++) {                       // 96 uint4 per row / 32 lanes
        uint4 a = ra[t * 32 + lane];
        uint4 b = rb[t * 32 + lane];
        const uint32_t* au = (const uint32_t*)&a;
        const uint32_t* bu = (const uint32_t*)&b;
        #pragma unroll
        for (int u = 0; u < 4; u++) {
            float2 fa = __bfloat1622float2(*(const __nv_bfloat162*)&au[u]);
            float2 fb = __bfloat1622float2(*(const __nv_bfloat162*)&bu[u]);
            acc = fmaf(fa.x, fb.x, acc);
            acc = fmaf(fa.y, fb.y, acc);
        }
    }
    #pragma unroll
    for (int o = 16; o; o >>= 1) acc += __shfl_down_sync(0xffffffffu, acc, o);

    __shared__ float sw8[8];
    if (lane == 0) sw8[w] = 1.0f - acc;
    __syncthreads();
    if (threadIdx.x == 0) {
        float t = 0.f;
        #pragma unroll
        for (int u = 0; u < 8; u++) t += sw8[u];
        g_pl[blockIdx.x] = t;
    }
}

// ---------------- 6) final scalar ----------------
__global__ void k_final(float* out) {
    float v = 0.f;
    for (int t = threadIdx.x; t < HW / 8; t += 256) v += g_pl[t];
    float tot = blk_sum(v);
    if (threadIdx.x == 0) out[0] = tot * (1.0f / HW);
}

// ---------------- launch ----------------
extern "C" void kernel_launch(void* const* d_in, const int* in_sizes, int n_in,
                              void* d_out, int out_size) {
    const float* x = (const float*)d_in[0];
    const float* s = (const float*)d_in[1];
    float* out = (float*)d_out;

    cudaFuncSetAttribute(k_gemm, cudaFuncAttributeMaxDynamicSharedMemorySize, 98304);
    cudaFuncSetAttribute(k_normhat, cudaFuncAttributeMaxDynamicSharedMemorySize, 49152);

    k_mean<<<dim3(CC, 2), 256>>>(x, s);
    k_normhat<<<dim3(HW / 64, 2), 256, 49152>>>(x, s);
    k_gemm<<<dim3(NJB, HW / 128), 256, 98304>>>();
    k_reduce<<<HW / 64, 256>>>();
    k_loss<<<HW / 8, 256>>>();
    k_final<<<1, 256>>>(out);
}

// round 17
// speedup vs baseline: 1.0216x; 1.0216x over previous
#include <cuda_runtime.h>
#include <cuda_bf16.h>
#include <cuda_fp16.h>
#include <cstdint>

#define HW 16384
#define CC 768
#define EPSF 1e-8f
#define NCH 12           // 768 / 64 K-chunks
#define BK 64
#define STG_BYTES 49152u // A 16KB + B 32KB per stage

// ---------------- scratch (device globals; no allocs allowed) ----------------
__device__ __align__(16) __half g_Ahat[(size_t)HW * CC];          // centered-normalized fp16, (i,c)
__device__ __align__(16) __half g_Bhat[(size_t)HW * CC];
__device__ __align__(16) __nv_bfloat16 g_Araw[(size_t)HW * CC];   // raw-normalized (loss)
__device__ __align__(16) __nv_bfloat16 g_Braw[(size_t)HW * CC];
__device__ float g_mean[2][CC];
__device__ unsigned long long g_best[HW];                         // packed (sortable(val)<<32)|~j
__device__ float g_pl[HW / 8];

// ---------------- helpers ----------------
static __device__ __forceinline__ uint32_t smem_u32(const void* p) {
    uint32_t a;
    asm("{ .reg .u64 t; cvta.to.shared.u64 t, %1; cvt.u32.u64 %0, t; }" : "=r"(a) : "l"(p));
    return a;
}
static __device__ __forceinline__ uint32_t sortable(float f) {
    uint32_t u = __float_as_uint(f);
    return (u & 0x80000000u) ? ~u : (u | 0x80000000u);
}

// ---------------- block reduce (sum) ----------------
static __device__ __forceinline__ float blk_sum(float v) {
    __shared__ float smr[32];
    int lane = threadIdx.x & 31, w = threadIdx.x >> 5;
    #pragma unroll
    for (int o = 16; o; o >>= 1) v += __shfl_down_sync(0xffffffffu, v, o);
    if (lane == 0) smr[w] = v;
    __syncthreads();
    if (w == 0) {
        v = (lane < (int)(blockDim.x >> 5)) ? smr[lane] : 0.f;
        #pragma unroll
        for (int o = 16; o; o >>= 1) v += __shfl_down_sync(0xffffffffu, v, o);
    }
    return v;  // valid in thread 0
}

// ---------------- 0) zero the argmax accumulator (graph replays!) ----------------
__global__ void k_init() {
    g_best[blockIdx.x * 256 + threadIdx.x] = 0ull;
}

// ---------------- 1) per-channel means (float4 loads) ----------------
__global__ void k_mean(const float* __restrict__ x, const float* __restrict__ s) {
    const float* p = blockIdx.y ? s : x;
    const float4* row = (const float4*)(p + (size_t)blockIdx.x * HW);
    float acc = 0.f;
    #pragma unroll 4
    for (int i = threadIdx.x; i < HW / 4; i += 256) {
        float4 v = row[i];
        acc += (v.x + v.y) + (v.z + v.w);
    }
    float t = blk_sum(acc);
    if (threadIdx.x == 0) g_mean[blockIdx.y][blockIdx.x] = t * (1.0f / HW);
}

// ---------------- 2) fused norms + fp16 hat + bf16 raw, 4 threads/position ------
__global__ void __launch_bounds__(256) k_normhat(const float* __restrict__ x,
                                                 const float* __restrict__ s) {
    extern __shared__ char dummy[];   // occupancy cap only
    (void)dummy;
    const int m = blockIdx.y;
    const float* p = m ? s : x;
    __half* dh = m ? g_Bhat : g_Ahat;
    __nv_bfloat16* dr = m ? g_Braw : g_Araw;
    const int i = blockIdx.x * 64 + (threadIdx.x >> 2);
    const int q = threadIdx.x & 3;          // channel quarter [q*192, q*192+192)
    const int c0 = q * 192;

    float ac = 0.f, ar = 0.f;
    #pragma unroll 8
    for (int k = 0; k < 192; k++) {
        int c = c0 + k;
        float v = p[(size_t)c * HW + i];
        float d = v - g_mean[m][c];
        ac = fmaf(d, d, ac);
        ar = fmaf(v, v, ar);
    }
    #pragma unroll
    for (int o = 1; o < 4; o <<= 1) {
        ac += __shfl_xor_sync(0xffffffffu, ac, o);
        ar += __shfl_xor_sync(0xffffffffu, ar, o);
    }
    float invc = 1.0f / (sqrtf(ac + EPSF) + EPSF);
    float invr = 1.0f / (sqrtf(ar) + EPSF);

    for (int k = 0; k < 192; k += 8) {
        uint4 wh, wr;
        uint32_t* ph = (uint32_t*)&wh;
        uint32_t* pr = (uint32_t*)&wr;
        #pragma unroll
        for (int u = 0; u < 4; u++) {
            int c = c0 + k + 2 * u;
            float v0 = p[(size_t)c * HW + i];
            float v1 = p[(size_t)(c + 1) * HW + i];
            __half2 h = __floats2half2_rn((v0 - g_mean[m][c]) * invc,
                                          (v1 - g_mean[m][c + 1]) * invc);
            __nv_bfloat162 r = __floats2bfloat162_rn(v0 * invr, v1 * invr);
            ph[u] = *(const uint32_t*)&h;
            pr[u] = *(const uint32_t*)&r;
        }
        *(uint4*)(dh + (size_t)i * CC + c0 + k) = wh;
        *(uint4*)(dr + (size_t)i * CC + c0 + k) = wr;
    }
}

// ---------------- 3) HMMA GEMM, CTA tile 128x256, 8 warps x (64x64), fp16 acc ---
// smem: 2 stages x (A 128x64 = 16KB + B 256x64 = 32KB) = 96KB, SW128 swizzle.
// Row argmax fused; per-row result merged chip-wide via deterministic atomicMax.
__global__ void __launch_bounds__(256, 2) k_gemm() {
    extern __shared__ char sm[];
    const int tid = threadIdx.x, wid = tid >> 5, lid = tid & 31;
    const int wm = wid >> 2, wn = wid & 3;       // warp 64x64 tile at (wm*64, wn*64)
    const uint32_t sbase = smem_u32(sm);

    const __half* Ag = g_Ahat + (size_t)blockIdx.y * 128 * CC;
    const __half* Bg = g_Bhat + (size_t)blockIdx.x * 256 * CC;

    const int lrow = tid >> 3;          // 0..31
    const int lq   = tid & 7;           // 16B chunk within 128B row

    auto load_stage = [&](int stg, int kc) {
        uint32_t abase = sbase + (uint32_t)stg * STG_BYTES;
        uint32_t bbase = abase + 16384u;
        const __half* ga = Ag + kc * BK;
        const __half* gb = Bg + kc * BK;
        #pragma unroll
        for (int ps = 0; ps < 4; ps++) {            // A: 128 rows
            int row = lrow + ps * 32;
            uint32_t off = (uint32_t)(row * 128 + lq * 16);
            uint32_t sw = off ^ ((off >> 3) & 0x70);
            const char* pa = (const char*)(ga + (size_t)row * CC) + lq * 16;
            asm volatile("cp.async.cg.shared.global [%0], [%1], 16;" :: "r"(abase + sw), "l"(pa));
        }
        #pragma unroll
        for (int ps = 0; ps < 8; ps++) {            // B: 256 rows
            int row = lrow + ps * 32;
            uint32_t off = (uint32_t)(row * 128 + lq * 16);
            uint32_t sw = off ^ ((off >> 3) & 0x70);
            const char* pb = (const char*)(gb + (size_t)row * CC) + lq * 16;
            asm volatile("cp.async.cg.shared.global [%0], [%1], 16;" :: "r"(bbase + sw), "l"(pb));
        }
        asm volatile("cp.async.commit_group;" ::: "memory");
    };

    // fp16 accumulators: 2 regs per 16x8 tile, 4 m-tiles x 8 n-tiles
    uint32_t acc[4][8][2];
    #pragma unroll
    for (int a = 0; a < 4; a++)
        #pragma unroll
        for (int b = 0; b < 8; b++) { acc[a][b][0] = 0u; acc[a][b][1] = 0u; }

    load_stage(0, 0);

    const int mrow8 = lid & 7;   // row within 8x8
    const int mat   = lid >> 3;  // which of 4 matrices

    for (int kc = 0; kc < NCH; kc++) {
        asm volatile("cp.async.wait_group 0;" ::: "memory");
        __syncthreads();                             // loads visible + prev stage free
        if (kc + 1 < NCH) load_stage((kc + 1) & 1, kc + 1);

        const uint32_t abase = sbase + (uint32_t)(kc & 1) * STG_BYTES;
        const uint32_t bbase = abase + 16384u;

        #pragma unroll
        for (int k16 = 0; k16 < 4; k16++) {
            const int k0 = k16 * 16;
            uint32_t af[4][4];
            #pragma unroll
            for (int mt = 0; mt < 4; mt++) {
                int row = wm * 64 + mt * 16 + (mat & 1) * 8 + mrow8;
                int kcol = k0 + (mat >> 1) * 8;
                uint32_t off = (uint32_t)(row * 128 + kcol * 2);
                uint32_t sw = abase + (off ^ ((off >> 3) & 0x70));
                asm volatile("ldmatrix.sync.aligned.m8n8.x4.shared.b16 {%0,%1,%2,%3}, [%4];"
                             : "=r"(af[mt][0]), "=r"(af[mt][1]), "=r"(af[mt][2]), "=r"(af[mt][3])
                             : "r"(sw));
            }
            uint32_t bf[8][2];
            #pragma unroll
            for (int g = 0; g < 4; g++) {
                int nrow = wn * 64 + g * 16 + (mat >> 1) * 8 + mrow8;
                int kcol = k0 + (mat & 1) * 8;
                uint32_t off = (uint32_t)(nrow * 128 + kcol * 2);
                uint32_t sw = bbase + (off ^ ((off >> 3) & 0x70));
                asm volatile("ldmatrix.sync.aligned.m8n8.x4.shared.b16 {%0,%1,%2,%3}, [%4];"
                             : "=r"(bf[g * 2][0]), "=r"(bf[g * 2][1]),
                               "=r"(bf[g * 2 + 1][0]), "=r"(bf[g * 2 + 1][1])
                             : "r"(sw));
            }
            #pragma unroll
            for (int mt = 0; mt < 4; mt++)
                #pragma unroll
                for (int nt = 0; nt < 8; nt++)
                    asm volatile(
                        "mma.sync.aligned.m16n8k16.row.col.f16.f16.f16.f16 "
                        "{%0,%1}, {%2,%3,%4,%5}, {%6,%7}, {%0,%1};"
                        : "+r"(acc[mt][nt][0]), "+r"(acc[mt][nt][1])
                        : "r"(af[mt][0]), "r"(af[mt][1]), "r"(af[mt][2]), "r"(af[mt][3]),
                          "r"(bf[nt][0]), "r"(bf[nt][1]));
        }
    }

    // ---- epilogue: row argmax over the 256-col tile ----
    // red overlays stage-0 smem (last chunk kc=11 used stage 1; post-barrier no
    // warp touches stage 0 again).
    unsigned long long* red = (unsigned long long*)sm;  // [128][4]
    const int quad = lid >> 2, qlan = lid & 3;
    #pragma unroll
    for (int mt = 0; mt < 4; mt++) {
        #pragma unroll
        for (int h = 0; h < 2; h++) {                  // h=0: rows r, h=1: rows r+8
            unsigned long long pk = 0ull;
            #pragma unroll
            for (int nt = 0; nt < 8; nt++) {
                float2 fv = __half22float2(*(const __half2*)&acc[mt][nt][h]);
                #pragma unroll
                for (int e = 0; e < 2; e++) {
                    float v = e ? fv.y : fv.x;
                    int j = blockIdx.x * 256 + wn * 64 + nt * 8 + qlan * 2 + e;
                    unsigned long long cand =
                        ((unsigned long long)sortable(v) << 32) | (uint32_t)(0xFFFFFFFFu - j);
                    if (cand > pk) pk = cand;
                }
            }
            #pragma unroll
            for (int off = 1; off < 4; off <<= 1) {
                unsigned long long o = __shfl_xor_sync(0xffffffffu, pk, off);
                if (o > pk) pk = o;
            }
            if (qlan == 0) {
                int row = wm * 64 + mt * 16 + h * 8 + quad;
                red[row * 4 + wn] = pk;
            }
        }
    }
    __syncthreads();
    if (tid < 128) {
        unsigned long long pk = red[tid * 4];
        #pragma unroll
        for (int w = 1; w < 4; w++) {
            unsigned long long o = red[tid * 4 + w];
            if (o > pk) pk = o;
        }
        atomicMax(&g_best[blockIdx.y * 128 + tid], pk);
    }
}

// ---------------- 4) gathered raw-cosine loss, warp-per-position ----------------
__global__ void k_loss() {
    const int w = threadIdx.x >> 5, lane = threadIdx.x & 31;
    const int i = blockIdx.x * 8 + w;
    const int z = (int)(0xFFFFFFFFu - (uint32_t)g_best[i]);
    const uint4* ra = (const uint4*)(g_Araw + (size_t)i * CC);
    const uint4* rb = (const uint4*)(g_Braw + (size_t)z * CC);
    float acc = 0.f;
    #pragma unroll
    for (int t = 0; t < 3; t++) {                       // 96 uint4 per row / 32 lanes
        uint4 a = ra[t * 32 + lane];
        uint4 b = rb[t * 32 + lane];
        const uint32_t* au = (const uint32_t*)&a;
        const uint32_t* bu = (const uint32_t*)&b;
        #pragma unroll
        for (int u = 0; u < 4; u++) {
            float2 fa = __bfloat1622float2(*(const __nv_bfloat162*)&au[u]);
            float2 fb = __bfloat1622float2(*(const __nv_bfloat162*)&bu[u]);
            acc = fmaf(fa.x, fb.x, acc);
            acc = fmaf(fa.y, fb.y, acc);
        }
    }
    #pragma unroll
    for (int o = 16; o; o >>= 1) acc += __shfl_down_sync(0xffffffffu, acc, o);

    __shared__ float sw8[8];
    if (lane == 0) sw8[w] = 1.0f - acc;
    __syncthreads();
    if (threadIdx.x == 0) {
        float t = 0.f;
        #pragma unroll
        for (int u = 0; u < 8; u++) t += sw8[u];
        g_pl[blockIdx.x] = t;
    }
}

// ---------------- 5) final scalar ----------------
__global__ void k_final(float* out) {
    float v = 0.f;
    for (int t = threadIdx.x; t < HW / 8; t += 256) v += g_pl[t];
    float tot = blk_sum(v);
    if (threadIdx.x == 0) out[0] = tot * (1.0f / HW);
}

// ---------------- launch ----------------
extern "C" void kernel_launch(void* const* d_in, const int* in_sizes, int n_in,
                              void* d_out, int out_size) {
    const float* x = (const float*)d_in[0];
    const float* s = (const float*)d_in[1];
    float* out = (float*)d_out;

    cudaFuncSetAttribute(k_gemm, cudaFuncAttributeMaxDynamicSharedMemorySize, 98304);
    cudaFuncSetAttribute(k_normhat, cudaFuncAttributeMaxDynamicSharedMemorySize, 49152);

    k_init<<<HW / 256, 256>>>();
    k_mean<<<dim3(CC, 2), 256>>>(x, s);
    k_normhat<<<dim3(HW / 64, 2), 256, 49152>>>(x, s);
    k_gemm<<<dim3(HW / 256, HW / 128), 256, 98304>>>();
    k_loss<<<HW / 8, 256>>>();
    k_final<<<1, 256>>>(out);
}